// round 2
// baseline (speedup 1.0000x reference)
#include <cuda_runtime.h>

#define EPSV 1e-4f
#define T_LEN 4096
#define DH 1024
#define C3 3072
#define NTILE 128   // 4096 / 32

__device__ __forceinline__ float sigmoid_f(float x) {
    // 1 / (1 + e^-x): MUFU EX2 + MUFU RCP
    return __fdividef(1.0f, 1.0f + __expf(-x));
}

__device__ __forceinline__ float tanh_f(float x) {
    // 1 - 2/(e^{2x}+1): stable at both tails (e->inf => 1, e->0 => -1)
    float e = __expf(2.0f * x);
    return 1.0f - __fdividef(2.0f, e + 1.0f);
}

// Block: 256 threads = 8 warps. Each block owns (batch b, channels d0..d0+7),
// walks the full 4096-step sequence in 128 tiles of 32 timesteps.
// Warp w computes channel d0+w; lane l is the timestep within the tile.
// Loads/stores are transposed through smem for coalescing.
__global__ __launch_bounds__(256) void glru_scan_kernel(
    const float* __restrict__ x, float* __restrict__ out)
{
    const int b  = blockIdx.y;
    const int d0 = blockIdx.x * 8;
    const int tid = threadIdx.x;
    const int w  = tid >> 5;   // channel within group (compute mapping)
    const int l  = tid & 31;   // time lane (compute mapping)
    const int lt = tid >> 3;   // time row 0..31 (load mapping)
    const int lc = tid & 7;    // channel 0..7  (load mapping)

    __shared__ float s_in[3][8][33];   // [col][ch][t], pad 33 -> conflict-free LDS
    __shared__ float s_out[8][33];

    // Per-thread global pointers (load side)
    const float* pin = x + ((size_t)b * T_LEN + lt) * C3 + d0 + lc;
    float* pout = out + ((size_t)b * T_LEN + lt) * DH + d0 + lc;

    // Prefetch tile 0 into registers
    float r0 = pin[0];
    float r1 = pin[DH];
    float r2 = pin[2 * DH];
    pin += 32 * C3;

    float a_carry = 1.0f;   // running cumprod carry
    float s_carry = 0.0f;   // running cumsum carry

    for (int k = 0; k < NTILE; ++k) {
        __syncthreads();                       // smem_in free, s_out consumed
        s_in[0][lc][lt] = r0;
        s_in[1][lc][lt] = r1;
        s_in[2][lc][lt] = r2;
        if (k + 1 < NTILE) {                   // prefetch next tile (overlaps compute)
            r0 = pin[0];
            r1 = pin[DH];
            r2 = pin[2 * DH];
            pin += 32 * C3;
        }
        __syncthreads();                       // tile ready

        float xi = s_in[0][w][l];              // input pre-activation
        float xg = s_in[1][w][l];              // input/forget gate pre-act
        float xo = s_in[2][w][l];              // output gate pre-act

        float ig = sigmoid_f(xg);
        float fg = 1.0f - ig;                  // matches reference rounding
        float kv = tanh_f(xi) * ig;
        float og = sigmoid_f(xo);

        // Inclusive warp cumprod of forget gates
        float p = fg;
        #pragma unroll
        for (int off = 1; off < 32; off <<= 1) {
            float v = __shfl_up_sync(0xffffffffu, p, off);
            if (l >= off) p *= v;
        }
        float a = a_carry * p;                 // global cumprod at this t

        float term = __fdividef(kv, a + EPSV);

        // Inclusive warp cumsum of terms
        float c = term;
        #pragma unroll
        for (int off = 1; off < 32; off <<= 1) {
            float v = __shfl_up_sync(0xffffffffu, c, off);
            if (l >= off) c += v;
        }
        float s = s_carry + c;

        float y = a * s;
        float o = tanh_f(y) * og;

        // Carry update (use lane 31's inclusive values)
        a_carry *= __shfl_sync(0xffffffffu, p, 31);
        s_carry += __shfl_sync(0xffffffffu, c, 31);

        // Transpose output back for coalesced store
        s_out[w][l] = o;
        __syncthreads();                       // s_out ready (also fences s_in reads)
        pout[0] = s_out[lc][lt];
        pout += 32 * DH;
    }
}

extern "C" void kernel_launch(void* const* d_in, const int* in_sizes, int n_in,
                              void* d_out, int out_size)
{
    const float* x = (const float*)d_in[0];
    float* out = (float*)d_out;
    dim3 grid(DH / 8, 8);   // 128 channel-groups x 8 batches = 1024 blocks
    glru_scan_kernel<<<grid, 256>>>(x, out);
}

// round 3
// speedup vs baseline: 1.4923x; 1.4923x over previous
#include <cuda_runtime.h>

#define EPSV 1e-4f
#define T_LEN 4096
#define DH 1024
#define C3 3072
#define TT 128          // timesteps per tile (4 per lane)
#define NTILE 32        // 4096 / 128
#define PITCH 132       // smem row pitch in floats: 16B-aligned, conflict-free

__device__ __forceinline__ float sigmoid_f(float x) {
    return __fdividef(1.0f, 1.0f + __expf(-x));
}

__device__ __forceinline__ float tanh_f(float x) {
    // 1 - 2/(e^{2x}+1): stable at both tails
    float e = __expf(2.0f * x);
    return 1.0f - __fdividef(2.0f, e + 1.0f);
}

// Block: 256 threads = 8 warps, owns (batch b, channels d0..d0+7).
// Tile = 128 timesteps. Warp w computes channel d0+w; lane l owns
// timesteps 4l..4l+3 of the tile (sequential within lane, warp-scan across lanes).
// Loads/stores are float4 and transposed through padded smem.
__global__ __launch_bounds__(256) void glru_scan_kernel(
    const float* __restrict__ x, float* __restrict__ out)
{
    const int b   = blockIdx.y;
    const int d0  = blockIdx.x * 8;
    const int tid = threadIdx.x;
    const int w   = tid >> 5;        // channel within group (compute mapping)
    const int l   = tid & 31;        // lane = 4-timestep segment
    const int tl  = tid >> 1;        // time row 0..127 (load mapping)
    const int cq  = (tid & 1) * 4;   // channel quad 0 or 4 (load mapping)

    __shared__ float s_in[3][8][PITCH];
    __shared__ float s_out[8][PITCH];

    const float* pin = x + ((size_t)(b * T_LEN) + tl) * C3 + d0 + cq;
    float*      pout = out + ((size_t)(b * T_LEN) + tl) * DH + d0 + cq;

    // Prefetch tile 0
    float4 r0 = *(const float4*)(pin);
    float4 r1 = *(const float4*)(pin + DH);
    float4 r2 = *(const float4*)(pin + 2 * DH);
    pin += (size_t)TT * C3;

    float a_carry = 1.0f;   // running cumprod carry
    float s_carry = 0.0f;   // running cumsum carry

    for (int k = 0; k < NTILE; ++k) {
        __syncthreads();                       // prev tile fully consumed
        s_in[0][cq + 0][tl] = r0.x;  s_in[0][cq + 1][tl] = r0.y;
        s_in[0][cq + 2][tl] = r0.z;  s_in[0][cq + 3][tl] = r0.w;
        s_in[1][cq + 0][tl] = r1.x;  s_in[1][cq + 1][tl] = r1.y;
        s_in[1][cq + 2][tl] = r1.z;  s_in[1][cq + 3][tl] = r1.w;
        s_in[2][cq + 0][tl] = r2.x;  s_in[2][cq + 1][tl] = r2.y;
        s_in[2][cq + 2][tl] = r2.z;  s_in[2][cq + 3][tl] = r2.w;
        if (k + 1 < NTILE) {                   // prefetch next tile
            r0 = *(const float4*)(pin);
            r1 = *(const float4*)(pin + DH);
            r2 = *(const float4*)(pin + 2 * DH);
            pin += (size_t)TT * C3;
        }
        __syncthreads();                       // tile ready

        float4 xi = *(const float4*)&s_in[0][w][4 * l];
        float4 xg = *(const float4*)&s_in[1][w][4 * l];
        float4 xo = *(const float4*)&s_in[2][w][4 * l];

        float fg[4], kv[4], og[4];
        {
            const float vxi[4] = {xi.x, xi.y, xi.z, xi.w};
            const float vxg[4] = {xg.x, xg.y, xg.z, xg.w};
            const float vxo[4] = {xo.x, xo.y, xo.z, xo.w};
            #pragma unroll
            for (int j = 0; j < 4; ++j) {
                float ig = sigmoid_f(vxg[j]);
                fg[j] = 1.0f - ig;
                kv[j] = tanh_f(vxi[j]) * ig;
                og[j] = sigmoid_f(vxo[j]);
            }
        }

        // Lane-local inclusive cumprod of forget gates
        float pc[4];
        pc[0] = fg[0];
        pc[1] = pc[0] * fg[1];
        pc[2] = pc[1] * fg[2];
        pc[3] = pc[2] * fg[3];

        // Warp inclusive scan (product) of lane totals
        float incP = pc[3];
        #pragma unroll
        for (int off = 1; off < 32; off <<= 1) {
            float v = __shfl_up_sync(0xffffffffu, incP, off);
            if (l >= off) incP *= v;
        }
        float exP = __shfl_up_sync(0xffffffffu, incP, 1);
        if (l == 0) exP = 1.0f;
        const float abase = a_carry * exP;

        float a[4], term[4];
        #pragma unroll
        for (int j = 0; j < 4; ++j) {
            a[j]    = abase * pc[j];
            term[j] = __fdividef(kv[j], a[j] + EPSV);
        }

        // Lane-local inclusive cumsum of terms
        float sc[4];
        sc[0] = term[0];
        sc[1] = sc[0] + term[1];
        sc[2] = sc[1] + term[2];
        sc[3] = sc[2] + term[3];

        // Warp inclusive scan (sum) of lane totals
        float incS = sc[3];
        #pragma unroll
        for (int off = 1; off < 32; off <<= 1) {
            float v = __shfl_up_sync(0xffffffffu, incS, off);
            if (l >= off) incS += v;
        }
        float exS = __shfl_up_sync(0xffffffffu, incS, 1);
        if (l == 0) exS = 0.0f;
        const float sbase = s_carry + exS;

        float4 o;
        o.x = tanh_f(a[0] * (sbase + sc[0])) * og[0];
        o.y = tanh_f(a[1] * (sbase + sc[1])) * og[1];
        o.z = tanh_f(a[2] * (sbase + sc[2])) * og[2];
        o.w = tanh_f(a[3] * (sbase + sc[3])) * og[3];

        // Carry update from lane 31's inclusive totals
        a_carry *= __shfl_sync(0xffffffffu, incP, 31);
        s_carry += __shfl_sync(0xffffffffu, incS, 31);

        // Transpose outputs back for coalesced float4 store
        *(float4*)&s_out[w][4 * l] = o;
        __syncthreads();                       // s_out ready
        float4 ov;
        ov.x = s_out[cq + 0][tl];
        ov.y = s_out[cq + 1][tl];
        ov.z = s_out[cq + 2][tl];
        ov.w = s_out[cq + 3][tl];
        *(float4*)pout = ov;
        pout += (size_t)TT * DH;
    }
}

extern "C" void kernel_launch(void* const* d_in, const int* in_sizes, int n_in,
                              void* d_out, int out_size)
{
    const float* x = (const float*)d_in[0];
    float* out = (float*)d_out;
    dim3 grid(DH / 8, 8);   // 128 channel-groups x 8 batches = 1024 blocks
    glru_scan_kernel<<<grid, 256>>>(x, out);
}